// round 1
// baseline (speedup 1.0000x reference)
#include <cuda_runtime.h>
#include <math_constants.h>
#include <cstdint>

// Problem constants
#define B_   2
#define S_   2048
#define D_   1024
#define H_   16
#define HD_  64
#define SCALE_ 0.125f   // 1/sqrt(64)

// ----------------------------------------------------------------------------
// Static device scratch (allocation-free rule: __device__ globals)
// ----------------------------------------------------------------------------
__device__ float g_qkv[(size_t)(B_*S_) * (3*D_)];        // [4096, 3072]  50.3 MB
__device__ float g_Qh [(size_t)B_*H_*S_*HD_];            // [B,H,S,HD]    16.8 MB
__device__ float g_Kh [(size_t)B_*H_*S_*HD_];
__device__ float g_Vh [(size_t)B_*H_*S_*HD_];
__device__ float g_attn[(size_t)(B_*S_) * D_];           // [4096, 1024]  16.8 MB

// ----------------------------------------------------------------------------
// Tiled fp32 GEMM: C[M,N] = A[M,K] @ B[K,N], all row-major.
// BM=BN=128, BK=16, 256 threads, 8x8 per thread. M,N,K multiples of tile dims.
// ----------------------------------------------------------------------------
#define BM 128
#define BN 128
#define BK 16
#define TM 8
#define TN 8

__global__ __launch_bounds__(256) void gemm_kernel(
    const float* __restrict__ A, const float* __restrict__ Bm,
    float* __restrict__ C, int M, int N, int K)
{
    __shared__ float As[BK][BM];   // A tile, transposed for broadcast reads
    __shared__ float Bs[BK][BN];

    const int tid  = threadIdx.x;
    const int brow = blockIdx.y;
    const int bcol = blockIdx.x;

    const int trow = (tid / 16) * TM;   // 0..120
    const int tcol = (tid % 16) * TN;   // 0..120

    float acc[TM][TN];
    #pragma unroll
    for (int i = 0; i < TM; i++)
        #pragma unroll
        for (int j = 0; j < TN; j++) acc[i][j] = 0.f;

    const int a_r0 = tid / 4;        // 0..63   (2 iters of 64 rows)
    const int a_c4 = tid % 4;        // float4 col 0..3
    const int b_r0 = tid / 32;       // 0..7    (2 iters of 8 rows)
    const int b_c4 = tid % 32;       // float4 col 0..31

    for (int kt = 0; kt < K; kt += BK) {
        // Load A tile (BM x BK), store transposed
        #pragma unroll
        for (int it = 0; it < 2; it++) {
            int r = a_r0 + it * 64;
            float4 v = *(const float4*)&A[(size_t)(brow*BM + r) * K + kt + a_c4*4];
            As[a_c4*4 + 0][r] = v.x;
            As[a_c4*4 + 1][r] = v.y;
            As[a_c4*4 + 2][r] = v.z;
            As[a_c4*4 + 3][r] = v.w;
        }
        // Load B tile (BK x BN)
        #pragma unroll
        for (int it = 0; it < 2; it++) {
            int r = b_r0 + it * 8;
            *(float4*)&Bs[r][b_c4*4] =
                *(const float4*)&Bm[(size_t)(kt + r) * N + bcol*BN + b_c4*4];
        }
        __syncthreads();

        #pragma unroll
        for (int k = 0; k < BK; k++) {
            float ra[TM], rb[TN];
            #pragma unroll
            for (int i = 0; i < TM; i += 4) {
                float4 v = *(const float4*)&As[k][trow + i];
                ra[i] = v.x; ra[i+1] = v.y; ra[i+2] = v.z; ra[i+3] = v.w;
            }
            #pragma unroll
            for (int j = 0; j < TN; j += 4) {
                float4 v = *(const float4*)&Bs[k][tcol + j];
                rb[j] = v.x; rb[j+1] = v.y; rb[j+2] = v.z; rb[j+3] = v.w;
            }
            #pragma unroll
            for (int i = 0; i < TM; i++)
                #pragma unroll
                for (int j = 0; j < TN; j++)
                    acc[i][j] += ra[i] * rb[j];
        }
        __syncthreads();
    }

    #pragma unroll
    for (int i = 0; i < TM; i++) {
        float* cr = &C[(size_t)(brow*BM + trow + i) * N + bcol*BN + tcol];
        #pragma unroll
        for (int j = 0; j < TN; j += 4) {
            float4 v = make_float4(acc[i][j], acc[i][j+1], acc[i][j+2], acc[i][j+3]);
            *(float4*)(cr + j) = v;
        }
    }
}

// ----------------------------------------------------------------------------
// RoPE + split + head-major reshape.
// qkv[b,s, 0:D]=q, [D:2D]=k, [2D:3D]=v.  Heads: dim index h*HD+d.
// rope(x)[d] = x[d]*cos[s,d] + (d<32 ? -x[d+32] : x[d-32]) * sin[s,d]
// Outputs in [B,H,S,HD].
// ----------------------------------------------------------------------------
__global__ __launch_bounds__(256) void rope_split_kernel(
    const float* __restrict__ qkv,
    const float* __restrict__ sin_q, const float* __restrict__ cos_q,
    const float* __restrict__ sin_k, const float* __restrict__ cos_k,
    float* __restrict__ Qh, float* __restrict__ Kh, float* __restrict__ Vh)
{
    int idx = blockIdx.x * blockDim.x + threadIdx.x;   // over B*S*D
    if (idx >= B_*S_*D_) return;
    int d = idx % HD_;
    int h = (idx / HD_) % H_;
    int s = (idx / D_) % S_;
    int b = idx / (S_ * D_);

    const float* row = qkv + ((size_t)b*S_ + s) * (3*D_);
    int hd = h*HD_ + d;
    int dp = (d < HD_/2) ? d + HD_/2 : d - HD_/2;
    float sgn = (d < HD_/2) ? -1.f : 1.f;

    float qv = row[hd];
    float kv = row[D_ + hd];
    float vv = row[2*D_ + hd];
    float qp = row[h*HD_ + dp];
    float kp = row[D_ + h*HD_ + dp];

    float sq = sin_q[s*HD_ + d], cq = cos_q[s*HD_ + d];
    float sk = sin_k[s*HD_ + d], ck = cos_k[s*HD_ + d];

    size_t o = (((size_t)b*H_ + h)*S_ + s) * HD_ + d;
    Qh[o] = qv * cq + sgn * qp * sq;
    Kh[o] = kv * ck + sgn * kp * sk;
    Vh[o] = vv;
}

// ----------------------------------------------------------------------------
// Causal flash attention, fp32. Thread-per-query, 128 queries per CTA,
// 32-key K/V tiles in smem, per-tile two-pass online softmax (scores in smem).
// Writes output directly in [B,S,D] layout (h*HD+d within D).
// ----------------------------------------------------------------------------
#define QB 128
#define KB 32

__global__ __launch_bounds__(QB, 1) void attn_kernel(
    const float* __restrict__ Qh, const float* __restrict__ Kh,
    const float* __restrict__ Vh, float* __restrict__ Oattn)
{
    __shared__ float Ks[KB * HD_];
    __shared__ float Vs[KB * HD_];
    __shared__ float Ps[KB][QB];

    const int bh   = blockIdx.y;           // b*H + h
    const int q0   = blockIdx.x * QB;
    const int t    = threadIdx.x;
    const int qpos = q0 + t;

    const float* Qp = Qh + ((size_t)bh*S_ + qpos) * HD_;
    float q[HD_];
    #pragma unroll
    for (int d = 0; d < HD_; d += 4) {
        float4 v = *(const float4*)(Qp + d);
        q[d] = v.x; q[d+1] = v.y; q[d+2] = v.z; q[d+3] = v.w;
    }

    float acc[HD_];
    #pragma unroll
    for (int d = 0; d < HD_; d++) acc[d] = 0.f;
    float m = -CUDART_INF_F;
    float l = 0.f;

    const float* Kbase = Kh + (size_t)bh * S_ * HD_;
    const float* Vbase = Vh + (size_t)bh * S_ * HD_;

    const int kend = q0 + QB;   // keys [0, kend) needed for this query block
    for (int k0 = 0; k0 < kend; k0 += KB) {
        // Cooperative tile load: KB*HD = 2048 floats = 512 float4, 4 per thread
        const float4* Kg = (const float4*)(Kbase + (size_t)k0 * HD_);
        const float4* Vg = (const float4*)(Vbase + (size_t)k0 * HD_);
        #pragma unroll
        for (int it = 0; it < (KB*HD_/4)/QB; it++) {
            int i = t + it * QB;
            ((float4*)Ks)[i] = Kg[i];
            ((float4*)Vs)[i] = Vg[i];
        }
        __syncthreads();

        // Pass 1: scores + tile max
        float mt = m;
        const bool full = (k0 + KB) <= (qpos + 1);   // all KB keys valid
        #pragma unroll 4
        for (int j = 0; j < KB; j++) {
            const float* kr = Ks + j * HD_;
            float s = 0.f;
            #pragma unroll
            for (int d = 0; d < HD_; d += 4) {
                float4 kv = *(const float4*)(kr + d);
                s += q[d]*kv.x + q[d+1]*kv.y + q[d+2]*kv.z + q[d+3]*kv.w;
            }
            s *= SCALE_;
            if (!full && (k0 + j) > qpos) s = -CUDART_INF_F;
            Ps[j][t] = s;
            mt = fmaxf(mt, s);
        }

        // Rescale accumulators once per tile
        float corr = __expf(m - mt);
        m = mt;
        l *= corr;
        #pragma unroll
        for (int d = 0; d < HD_; d++) acc[d] *= corr;

        // Pass 2: exp + PV accumulate
        #pragma unroll 4
        for (int j = 0; j < KB; j++) {
            float pj = __expf(Ps[j][t] - m);
            l += pj;
            const float* vr = Vs + j * HD_;
            #pragma unroll
            for (int d = 0; d < HD_; d += 4) {
                float4 vv = *(const float4*)(vr + d);
                acc[d]   += pj * vv.x;
                acc[d+1] += pj * vv.y;
                acc[d+2] += pj * vv.z;
                acc[d+3] += pj * vv.w;
            }
        }
        __syncthreads();
    }

    // Write [B,S,D] with in-D offset h*HD
    const int b = bh / H_, h = bh % H_;
    const float inv = 1.f / l;
    float* Op = Oattn + ((size_t)b*S_ + qpos) * D_ + h*HD_;
    #pragma unroll
    for (int d = 0; d < HD_; d += 4) {
        float4 v = make_float4(acc[d]*inv, acc[d+1]*inv, acc[d+2]*inv, acc[d+3]*inv);
        *(float4*)(Op + d) = v;
    }
}

// ----------------------------------------------------------------------------
// Launch
// ----------------------------------------------------------------------------
extern "C" void kernel_launch(void* const* d_in, const int* in_sizes, int n_in,
                              void* d_out, int out_size)
{
    const float* query = (const float*)d_in[0];
    const float* sin_q = (const float*)d_in[1];
    const float* cos_q = (const float*)d_in[2];
    const float* sin_k = (const float*)d_in[3];
    const float* cos_k = (const float*)d_in[4];
    const float* w_in  = (const float*)d_in[5];
    const float* w_out = (const float*)d_in[6];
    float* out = (float*)d_out;

    float *qkv, *Qh, *Kh, *Vh, *attn;
    cudaGetSymbolAddress((void**)&qkv,  g_qkv);
    cudaGetSymbolAddress((void**)&Qh,   g_Qh);
    cudaGetSymbolAddress((void**)&Kh,   g_Kh);
    cudaGetSymbolAddress((void**)&Vh,   g_Vh);
    cudaGetSymbolAddress((void**)&attn, g_attn);

    const int M = B_ * S_;   // 4096

    // 1) QKV projection: [4096,1024] @ [1024,3072]
    gemm_kernel<<<dim3((3*D_)/BN, M/BM), 256>>>(query, w_in, qkv, M, 3*D_, D_);

    // 2) RoPE + split into head-major Q/K/V
    rope_split_kernel<<<(B_*S_*D_ + 255)/256, 256>>>(
        qkv, sin_q, cos_q, sin_k, cos_k, Qh, Kh, Vh);

    // 3) Causal flash attention
    attn_kernel<<<dim3(S_/QB, B_*H_), QB>>>(Qh, Kh, Vh, attn);

    // 4) Output projection: [4096,1024] @ [1024,1024]
    gemm_kernel<<<dim3(D_/BN, M/BM), 256>>>(attn, w_out, out, M, D_, D_);
}

// round 3
// speedup vs baseline: 1.3022x; 1.3022x over previous
#include <cuda_runtime.h>
#include <cuda_bf16.h>
#include <math_constants.h>
#include <cstdint>

// Problem constants
#define B_   2
#define S_   2048
#define D_   1024
#define H_   16
#define HD_  64
#define SCALE_ 0.125f   // 1/sqrt(64)
#define KP_  (3 * D_)   // compensated K' = 3072

// ============================================================================
// Static device scratch
// ============================================================================
__device__ float g_qkv [(size_t)(B_*S_) * (3*D_)];
__device__ float g_Qh  [(size_t)B_*H_*S_*HD_];
__device__ float g_Kh  [(size_t)B_*H_*S_*HD_];
__device__ float g_Vh  [(size_t)B_*H_*S_*HD_];
__device__ float g_attn[(size_t)(B_*S_) * D_];
__device__ __nv_bfloat16 g_Abig [(size_t)(B_*S_) * KP_];   // [4096, 3072] bf16
__device__ __nv_bfloat16 g_W1big[(size_t)(3*D_) * KP_];    // [3072, 3072] bf16
__device__ __nv_bfloat16 g_W2big[(size_t)D_ * KP_];        // [1024, 3072] bf16

// ============================================================================
// PTX helpers (all sm_80-era, safe for compute_103 baseline PTX)
// ============================================================================
__device__ __forceinline__ uint32_t smem_u32(const void* p) {
    uint32_t a;
    asm("{ .reg .u64 t; cvta.to.shared.u64 t, %1; cvt.u32.u64 %0, t; }" : "=r"(a) : "l"(p));
    return a;
}
#define CP_ASYNC16(saddr, gptr) \
    asm volatile("cp.async.cg.shared.global [%0], [%1], 16;" :: "r"(saddr), "l"(gptr))
#define CP_COMMIT() asm volatile("cp.async.commit_group;" ::: "memory")
#define CP_WAIT1()  asm volatile("cp.async.wait_group 1;" ::: "memory")
#define CP_WAIT0()  asm volatile("cp.async.wait_group 0;" ::: "memory")
#define LDMATRIX_X4(r0, r1, r2, r3, addr) \
    asm volatile("ldmatrix.sync.aligned.m8n8.x4.shared.b16 {%0,%1,%2,%3}, [%4];" \
        : "=r"(r0), "=r"(r1), "=r"(r2), "=r"(r3) : "r"(addr))
#define MMA_BF16(c0, c1, c2, c3, a0, a1, a2, a3, b0, b1) \
    asm volatile("mma.sync.aligned.m16n8k16.row.col.f32.bf16.bf16.f32 " \
        "{%0,%1,%2,%3}, {%4,%5,%6,%7}, {%8,%9}, {%0,%1,%2,%3};" \
        : "+f"(c0), "+f"(c1), "+f"(c2), "+f"(c3) \
        : "r"(a0), "r"(a1), "r"(a2), "r"(a3), "r"(b0), "r"(b1))

// ============================================================================
// Prep: bf16 hi/lo 3-term encode.
// A' [M, 3K]: [hi | lo | hi]; W' [N, 3K]: [hi | hi | lo] (W transposed to N-major)
// ============================================================================
__global__ __launch_bounds__(256) void split_a_kernel(
    const float* __restrict__ x, __nv_bfloat16* __restrict__ out, int total)
{
    int i = blockIdx.x * blockDim.x + threadIdx.x;   // over M*D
    if (i >= total) return;
    int r = i >> 10, c = i & (D_ - 1);
    float v = x[i];
    __nv_bfloat16 h = __float2bfloat16(v);
    __nv_bfloat16 l = __float2bfloat16(v - __bfloat162float(h));
    size_t base = (size_t)r * KP_;
    out[base + c]          = h;
    out[base + D_ + c]     = l;
    out[base + 2*D_ + c]   = h;
}

// w[K=1024][N] -> out[N][3K]: [hi | hi | lo]
__global__ __launch_bounds__(256) void transpose_split_w_kernel(
    const float* __restrict__ w, __nv_bfloat16* __restrict__ out, int N)
{
    __shared__ float tile[32][33];
    int k0 = blockIdx.y * 32, n0 = blockIdx.x * 32;
    int tx = threadIdx.x, ty = threadIdx.y;
    #pragma unroll
    for (int i = 0; i < 32; i += 8)
        tile[ty + i][tx] = w[(size_t)(k0 + ty + i) * N + n0 + tx];
    __syncthreads();
    #pragma unroll
    for (int i = 0; i < 32; i += 8) {
        float x = tile[tx][ty + i];   // = w[k0+tx][n0+ty+i]
        __nv_bfloat16 h = __float2bfloat16(x);
        __nv_bfloat16 l = __float2bfloat16(x - __bfloat162float(h));
        size_t o = (size_t)(n0 + ty + i) * KP_ + k0 + tx;
        out[o]          = h;
        out[o + D_]     = h;
        out[o + 2*D_]   = l;
    }
}

// ============================================================================
// bf16 mma.sync GEMM: C[M,N] = A'[M,KP] @ W'[N,KP]^T, fp32 accumulate.
// CTA tile 128x128, BK=32, 8 warps (2x4) of 64x32, 2-stage cp.async pipeline.
// ============================================================================
#define GBM 128
#define GBN 128
#define GBK 32
#define SSTRIDE 40   // bf16 elems per smem row (32 + 8 pad -> 80B, conflict-free)

__global__ __launch_bounds__(256) void gemm_mma_kernel(
    const __nv_bfloat16* __restrict__ A,   // [M, KP]
    const __nv_bfloat16* __restrict__ W,   // [N, KP]
    float* __restrict__ C, int M, int N)
{
    __shared__ __nv_bfloat16 As[2][GBM * SSTRIDE];
    __shared__ __nv_bfloat16 Bs[2][GBN * SSTRIDE];

    const int tid  = threadIdx.x;
    const int wid  = tid >> 5, lane = tid & 31;
    const int m0   = blockIdx.y * GBM;
    const int n0   = blockIdx.x * GBN;
    const int wm   = wid >> 2;       // 0..1 -> 64 rows
    const int wn   = wid & 3;        // 0..3 -> 32 cols

    float acc[4][4][4];
    #pragma unroll
    for (int mi = 0; mi < 4; mi++)
        #pragma unroll
        for (int ni = 0; ni < 4; ni++)
            #pragma unroll
            for (int r = 0; r < 4; r++) acc[mi][ni][r] = 0.f;

    const uint32_t as0 = smem_u32(&As[0][0]), as1 = smem_u32(&As[1][0]);
    const uint32_t bs0 = smem_u32(&Bs[0][0]), bs1 = smem_u32(&Bs[1][0]);

    // Per-thread load coords: 512 float4 per tile, 2 per thread
    const int lr0 = tid >> 2,          lc0 = (tid & 3);          // row 0..63
    const int lr1 = (tid + 256) >> 2,  lc1 = (tid & 3);          // row 64..127

    auto load_stage = [&](int stage, int kb) {
        const int kt = kb * GBK;
        const uint32_t as = stage ? as1 : as0;
        const uint32_t bs = stage ? bs1 : bs0;
        CP_ASYNC16(as + (uint32_t)(lr0 * SSTRIDE + lc0 * 8) * 2,
                   A + (size_t)(m0 + lr0) * KP_ + kt + lc0 * 8);
        CP_ASYNC16(as + (uint32_t)(lr1 * SSTRIDE + lc1 * 8) * 2,
                   A + (size_t)(m0 + lr1) * KP_ + kt + lc1 * 8);
        CP_ASYNC16(bs + (uint32_t)(lr0 * SSTRIDE + lc0 * 8) * 2,
                   W + (size_t)(n0 + lr0) * KP_ + kt + lc0 * 8);
        CP_ASYNC16(bs + (uint32_t)(lr1 * SSTRIDE + lc1 * 8) * 2,
                   W + (size_t)(n0 + lr1) * KP_ + kt + lc1 * 8);
    };

    const int NKB = KP_ / GBK;   // 96
    load_stage(0, 0);
    CP_COMMIT();

    for (int kb = 0; kb < NKB; kb++) {
        if (kb + 1 < NKB) {
            load_stage((kb + 1) & 1, kb + 1);
            CP_COMMIT();
            CP_WAIT1();
        } else {
            CP_WAIT0();
        }
        __syncthreads();

        const uint32_t as = (kb & 1) ? as1 : as0;
        const uint32_t bs = (kb & 1) ? bs1 : bs0;

        #pragma unroll
        for (int ks = 0; ks < 2; ks++) {   // two k16 steps per BK
            uint32_t a[4][4];
            #pragma unroll
            for (int mi = 0; mi < 4; mi++) {
                int row = wm * 64 + mi * 16 + (lane & 15);
                int col = ks * 16 + (lane >> 4) * 8;
                LDMATRIX_X4(a[mi][0], a[mi][1], a[mi][2], a[mi][3],
                            as + (uint32_t)(row * SSTRIDE + col) * 2);
            }
            uint32_t b[4][2];
            #pragma unroll
            for (int nb = 0; nb < 2; nb++) {
                int nrow = wn * 32 + nb * 16 + ((lane & 16) ? 8 : 0) + (lane & 7);
                int kcol = ks * 16 + ((lane & 8) ? 8 : 0);
                uint32_t r0, r1, r2, r3;
                LDMATRIX_X4(r0, r1, r2, r3,
                            bs + (uint32_t)(nrow * SSTRIDE + kcol) * 2);
                b[nb*2][0] = r0; b[nb*2][1] = r1;
                b[nb*2+1][0] = r2; b[nb*2+1][1] = r3;
            }
            #pragma unroll
            for (int mi = 0; mi < 4; mi++)
                #pragma unroll
                for (int ni = 0; ni < 4; ni++)
                    MMA_BF16(acc[mi][ni][0], acc[mi][ni][1], acc[mi][ni][2], acc[mi][ni][3],
                             a[mi][0], a[mi][1], a[mi][2], a[mi][3],
                             b[ni][0], b[ni][1]);
        }
        __syncthreads();
    }

    // Epilogue: direct fp32 stores (float2 per fragment half)
    #pragma unroll
    for (int mi = 0; mi < 4; mi++) {
        int mrow = m0 + wm * 64 + mi * 16 + (lane >> 2);
        #pragma unroll
        for (int ni = 0; ni < 4; ni++) {
            int ncol = n0 + wn * 32 + ni * 8 + (lane & 3) * 2;
            *(float2*)&C[(size_t)mrow * N + ncol] =
                make_float2(acc[mi][ni][0], acc[mi][ni][1]);
            *(float2*)&C[(size_t)(mrow + 8) * N + ncol] =
                make_float2(acc[mi][ni][2], acc[mi][ni][3]);
        }
    }
}

// ============================================================================
// RoPE + split + head-major reshape (unchanged from R1)
// ============================================================================
__global__ __launch_bounds__(256) void rope_split_kernel(
    const float* __restrict__ qkv,
    const float* __restrict__ sin_q, const float* __restrict__ cos_q,
    const float* __restrict__ sin_k, const float* __restrict__ cos_k,
    float* __restrict__ Qh, float* __restrict__ Kh, float* __restrict__ Vh)
{
    int idx = blockIdx.x * blockDim.x + threadIdx.x;
    if (idx >= B_*S_*D_) return;
    int d = idx % HD_;
    int h = (idx / HD_) % H_;
    int s = (idx / D_) % S_;
    int b = idx / (S_ * D_);

    const float* row = qkv + ((size_t)b*S_ + s) * (3*D_);
    int hd = h*HD_ + d;
    int dp = (d < HD_/2) ? d + HD_/2 : d - HD_/2;
    float sgn = (d < HD_/2) ? -1.f : 1.f;

    float qv = row[hd];
    float kv = row[D_ + hd];
    float vv = row[2*D_ + hd];
    float qp = row[h*HD_ + dp];
    float kp = row[D_ + h*HD_ + dp];

    float sq = sin_q[s*HD_ + d], cq = cos_q[s*HD_ + d];
    float sk = sin_k[s*HD_ + d], ck = cos_k[s*HD_ + d];

    size_t o = (((size_t)b*H_ + h)*S_ + s) * HD_ + d;
    Qh[o] = qv * cq + sgn * qp * sq;
    Kh[o] = kv * ck + sgn * kp * sk;
    Vh[o] = vv;
}

// ============================================================================
// Causal flash attention, fp32 (unchanged from R1)
// ============================================================================
#define QB 128
#define KB 32

__global__ __launch_bounds__(QB, 1) void attn_kernel(
    const float* __restrict__ Qh, const float* __restrict__ Kh,
    const float* __restrict__ Vh, float* __restrict__ Oattn)
{
    __shared__ float Ks[KB * HD_];
    __shared__ float Vs[KB * HD_];
    __shared__ float Ps[KB][QB];

    const int bh   = blockIdx.y;
    const int q0   = blockIdx.x * QB;
    const int t    = threadIdx.x;
    const int qpos = q0 + t;

    const float* Qp = Qh + ((size_t)bh*S_ + qpos) * HD_;
    float q[HD_];
    #pragma unroll
    for (int d = 0; d < HD_; d += 4) {
        float4 v = *(const float4*)(Qp + d);
        q[d] = v.x; q[d+1] = v.y; q[d+2] = v.z; q[d+3] = v.w;
    }

    float acc[HD_];
    #pragma unroll
    for (int d = 0; d < HD_; d++) acc[d] = 0.f;
    float m = -CUDART_INF_F;
    float l = 0.f;

    const float* Kbase = Kh + (size_t)bh * S_ * HD_;
    const float* Vbase = Vh + (size_t)bh * S_ * HD_;

    const int kend = q0 + QB;
    for (int k0 = 0; k0 < kend; k0 += KB) {
        const float4* Kg = (const float4*)(Kbase + (size_t)k0 * HD_);
        const float4* Vg = (const float4*)(Vbase + (size_t)k0 * HD_);
        #pragma unroll
        for (int it = 0; it < (KB*HD_/4)/QB; it++) {
            int i = t + it * QB;
            ((float4*)Ks)[i] = Kg[i];
            ((float4*)Vs)[i] = Vg[i];
        }
        __syncthreads();

        float mt = m;
        const bool full = (k0 + KB) <= (qpos + 1);
        #pragma unroll 4
        for (int j = 0; j < KB; j++) {
            const float* kr = Ks + j * HD_;
            float s = 0.f;
            #pragma unroll
            for (int d = 0; d < HD_; d += 4) {
                float4 kv = *(const float4*)(kr + d);
                s += q[d]*kv.x + q[d+1]*kv.y + q[d+2]*kv.z + q[d+3]*kv.w;
            }
            s *= SCALE_;
            if (!full && (k0 + j) > qpos) s = -CUDART_INF_F;
            Ps[j][t] = s;
            mt = fmaxf(mt, s);
        }

        float corr = __expf(m - mt);
        m = mt;
        l *= corr;
        #pragma unroll
        for (int d = 0; d < HD_; d++) acc[d] *= corr;

        #pragma unroll 4
        for (int j = 0; j < KB; j++) {
            float pj = __expf(Ps[j][t] - m);
            l += pj;
            const float* vr = Vs + j * HD_;
            #pragma unroll
            for (int d = 0; d < HD_; d += 4) {
                float4 vv = *(const float4*)(vr + d);
                acc[d]   += pj * vv.x;
                acc[d+1] += pj * vv.y;
                acc[d+2] += pj * vv.z;
                acc[d+3] += pj * vv.w;
            }
        }
        __syncthreads();
    }

    const int b = bh / H_, h = bh % H_;
    const float inv = 1.f / l;
    float* Op = Oattn + ((size_t)b*S_ + qpos) * D_ + h*HD_;
    #pragma unroll
    for (int d = 0; d < HD_; d += 4) {
        float4 v = make_float4(acc[d]*inv, acc[d+1]*inv, acc[d+2]*inv, acc[d+3]*inv);
        *(float4*)(Op + d) = v;
    }
}

// ============================================================================
// Launch
// ============================================================================
extern "C" void kernel_launch(void* const* d_in, const int* in_sizes, int n_in,
                              void* d_out, int out_size)
{
    const float* query = (const float*)d_in[0];
    const float* sin_q = (const float*)d_in[1];
    const float* cos_q = (const float*)d_in[2];
    const float* sin_k = (const float*)d_in[3];
    const float* cos_k = (const float*)d_in[4];
    const float* w_in  = (const float*)d_in[5];
    const float* w_out = (const float*)d_in[6];
    float* out = (float*)d_out;

    float *qkv, *Qh, *Kh, *Vh, *attn;
    __nv_bfloat16 *Abig, *W1big, *W2big;
    cudaGetSymbolAddress((void**)&qkv,   g_qkv);
    cudaGetSymbolAddress((void**)&Qh,    g_Qh);
    cudaGetSymbolAddress((void**)&Kh,    g_Kh);
    cudaGetSymbolAddress((void**)&Vh,    g_Vh);
    cudaGetSymbolAddress((void**)&attn,  g_attn);
    cudaGetSymbolAddress((void**)&Abig,  g_Abig);
    cudaGetSymbolAddress((void**)&W1big, g_W1big);
    cudaGetSymbolAddress((void**)&W2big, g_W2big);

    const int M = B_ * S_;   // 4096

    // Prep: 3-term bf16 encode
    split_a_kernel<<<(M*D_ + 255)/256, 256>>>(query, Abig, M*D_);
    transpose_split_w_kernel<<<dim3(3*D_/32, D_/32), dim3(32,8)>>>(w_in,  W1big, 3*D_);
    transpose_split_w_kernel<<<dim3(D_/32,   D_/32), dim3(32,8)>>>(w_out, W2big, D_);

    // 1) QKV projection (tensor cores): [4096,3072] = A'[4096,3072] @ W1'[3072,3072]^T
    gemm_mma_kernel<<<dim3(3*D_/GBN, M/GBM), 256>>>(Abig, W1big, qkv, M, 3*D_);

    // 2) RoPE + split
    rope_split_kernel<<<(B_*S_*D_ + 255)/256, 256>>>(qkv, sin_q, cos_q, sin_k, cos_k, Qh, Kh, Vh);

    // 3) Causal flash attention (fp32)
    attn_kernel<<<dim3(S_/QB, B_*H_), QB>>>(Qh, Kh, Vh, attn);

    // 4) Output projection (tensor cores)
    split_a_kernel<<<(M*D_ + 255)/256, 256>>>(attn, Abig, M*D_);
    gemm_mma_kernel<<<dim3(D_/GBN, M/GBM), 256>>>(Abig, W2big, out, M, D_);
}

// round 4
// speedup vs baseline: 2.5702x; 1.9738x over previous
#include <cuda_runtime.h>
#include <cuda_bf16.h>
#include <math_constants.h>
#include <cstdint>

// Problem constants
#define B_   2
#define S_   2048
#define D_   1024
#define H_   16
#define HD_  64
#define SCALE_ 0.125f   // 1/sqrt(64)
#define KP_  (3 * D_)   // compensated K' = 3072 for projections
#define AKP_ 192        // compensated K' for QK^T (3*64)

// ============================================================================
// Static device scratch
// ============================================================================
__device__ float g_qkv [(size_t)(B_*S_) * (3*D_)];
__device__ float g_attn[(size_t)(B_*S_) * D_];
__device__ __nv_bfloat16 g_Abig [(size_t)(B_*S_) * KP_];
__device__ __nv_bfloat16 g_W1big[(size_t)(3*D_) * KP_];
__device__ __nv_bfloat16 g_W2big[(size_t)D_ * KP_];
__device__ __nv_bfloat16 g_Qp [(size_t)B_*H_*S_*AKP_];   // [Qh|Ql|Qh], scale folded
__device__ __nv_bfloat16 g_Kp [(size_t)B_*H_*S_*AKP_];   // [Kh|Kh|Kl]
__device__ __nv_bfloat16 g_Vph[(size_t)B_*H_*S_*HD_];
__device__ __nv_bfloat16 g_Vpl[(size_t)B_*H_*S_*HD_];

// ============================================================================
// PTX helpers (sm_80-era only — safe for compute_103 baseline PTX)
// ============================================================================
__device__ __forceinline__ uint32_t smem_u32(const void* p) {
    uint32_t a;
    asm("{ .reg .u64 t; cvta.to.shared.u64 t, %1; cvt.u32.u64 %0, t; }" : "=r"(a) : "l"(p));
    return a;
}
#define CP_ASYNC16(saddr, gptr) \
    asm volatile("cp.async.cg.shared.global [%0], [%1], 16;" :: "r"(saddr), "l"(gptr))
#define CP_COMMIT() asm volatile("cp.async.commit_group;" ::: "memory")
#define CP_WAIT1()  asm volatile("cp.async.wait_group 1;" ::: "memory")
#define CP_WAIT0()  asm volatile("cp.async.wait_group 0;" ::: "memory")
#define LDMATRIX_X4(r0, r1, r2, r3, addr) \
    asm volatile("ldmatrix.sync.aligned.m8n8.x4.shared.b16 {%0,%1,%2,%3}, [%4];" \
        : "=r"(r0), "=r"(r1), "=r"(r2), "=r"(r3) : "r"(addr))
#define LDMATRIX_X4_T(r0, r1, r2, r3, addr) \
    asm volatile("ldmatrix.sync.aligned.m8n8.x4.trans.shared.b16 {%0,%1,%2,%3}, [%4];" \
        : "=r"(r0), "=r"(r1), "=r"(r2), "=r"(r3) : "r"(addr))
#define MMA_BF16(c0, c1, c2, c3, a0, a1, a2, a3, b0, b1) \
    asm volatile("mma.sync.aligned.m16n8k16.row.col.f32.bf16.bf16.f32 " \
        "{%0,%1,%2,%3}, {%4,%5,%6,%7}, {%8,%9}, {%0,%1,%2,%3};" \
        : "+f"(c0), "+f"(c1), "+f"(c2), "+f"(c3) \
        : "r"(a0), "r"(a1), "r"(a2), "r"(a3), "r"(b0), "r"(b1))

__device__ __forceinline__ void pack_pair(float p0, float p1, uint32_t &h, uint32_t &l) {
    __nv_bfloat16 h0 = __float2bfloat16(p0), h1 = __float2bfloat16(p1);
    float r0 = p0 - __bfloat162float(h0);
    float r1 = p1 - __bfloat162float(h1);
    __nv_bfloat16 l0 = __float2bfloat16(r0), l1 = __float2bfloat16(r1);
    h = ((uint32_t)__bfloat16_as_ushort(h1) << 16) | (uint32_t)__bfloat16_as_ushort(h0);
    l = ((uint32_t)__bfloat16_as_ushort(l1) << 16) | (uint32_t)__bfloat16_as_ushort(l0);
}

// ============================================================================
// Prep: bf16 hi/lo 3-term encode for projections (unchanged from R3)
// ============================================================================
__global__ __launch_bounds__(256) void split_a_kernel(
    const float* __restrict__ x, __nv_bfloat16* __restrict__ out, int total)
{
    int i = blockIdx.x * blockDim.x + threadIdx.x;
    if (i >= total) return;
    int r = i >> 10, c = i & (D_ - 1);
    float v = x[i];
    __nv_bfloat16 h = __float2bfloat16(v);
    __nv_bfloat16 l = __float2bfloat16(v - __bfloat162float(h));
    size_t base = (size_t)r * KP_;
    out[base + c]        = h;
    out[base + D_ + c]   = l;
    out[base + 2*D_ + c] = h;
}

__global__ __launch_bounds__(256) void transpose_split_w_kernel(
    const float* __restrict__ w, __nv_bfloat16* __restrict__ out, int N)
{
    __shared__ float tile[32][33];
    int k0 = blockIdx.y * 32, n0 = blockIdx.x * 32;
    int tx = threadIdx.x, ty = threadIdx.y;
    #pragma unroll
    for (int i = 0; i < 32; i += 8)
        tile[ty + i][tx] = w[(size_t)(k0 + ty + i) * N + n0 + tx];
    __syncthreads();
    #pragma unroll
    for (int i = 0; i < 32; i += 8) {
        float x = tile[tx][ty + i];
        __nv_bfloat16 h = __float2bfloat16(x);
        __nv_bfloat16 l = __float2bfloat16(x - __bfloat162float(h));
        size_t o = (size_t)(n0 + ty + i) * KP_ + k0 + tx;
        out[o]        = h;
        out[o + D_]   = h;
        out[o + 2*D_] = l;
    }
}

// ============================================================================
// bf16 mma.sync GEMM (unchanged from R3 — 283us/95us, tensor 44.7%)
// ============================================================================
#define GBM 128
#define GBN 128
#define GBK 32
#define SSTRIDE 40

__global__ __launch_bounds__(256) void gemm_mma_kernel(
    const __nv_bfloat16* __restrict__ A,
    const __nv_bfloat16* __restrict__ W,
    float* __restrict__ C, int M, int N)
{
    __shared__ __nv_bfloat16 As[2][GBM * SSTRIDE];
    __shared__ __nv_bfloat16 Bs[2][GBN * SSTRIDE];

    const int tid  = threadIdx.x;
    const int wid  = tid >> 5, lane = tid & 31;
    const int m0   = blockIdx.y * GBM;
    const int n0   = blockIdx.x * GBN;
    const int wm   = wid >> 2;
    const int wn   = wid & 3;

    float acc[4][4][4];
    #pragma unroll
    for (int mi = 0; mi < 4; mi++)
        #pragma unroll
        for (int ni = 0; ni < 4; ni++)
            #pragma unroll
            for (int r = 0; r < 4; r++) acc[mi][ni][r] = 0.f;

    const uint32_t as0 = smem_u32(&As[0][0]), as1 = smem_u32(&As[1][0]);
    const uint32_t bs0 = smem_u32(&Bs[0][0]), bs1 = smem_u32(&Bs[1][0]);

    const int lr0 = tid >> 2,          lc0 = (tid & 3);
    const int lr1 = (tid + 256) >> 2,  lc1 = (tid & 3);

    auto load_stage = [&](int stage, int kb) {
        const int kt = kb * GBK;
        const uint32_t as = stage ? as1 : as0;
        const uint32_t bs = stage ? bs1 : bs0;
        CP_ASYNC16(as + (uint32_t)(lr0 * SSTRIDE + lc0 * 8) * 2,
                   A + (size_t)(m0 + lr0) * KP_ + kt + lc0 * 8);
        CP_ASYNC16(as + (uint32_t)(lr1 * SSTRIDE + lc1 * 8) * 2,
                   A + (size_t)(m0 + lr1) * KP_ + kt + lc1 * 8);
        CP_ASYNC16(bs + (uint32_t)(lr0 * SSTRIDE + lc0 * 8) * 2,
                   W + (size_t)(n0 + lr0) * KP_ + kt + lc0 * 8);
        CP_ASYNC16(bs + (uint32_t)(lr1 * SSTRIDE + lc1 * 8) * 2,
                   W + (size_t)(n0 + lr1) * KP_ + kt + lc1 * 8);
    };

    const int NKB = KP_ / GBK;
    load_stage(0, 0);
    CP_COMMIT();

    for (int kb = 0; kb < NKB; kb++) {
        if (kb + 1 < NKB) {
            load_stage((kb + 1) & 1, kb + 1);
            CP_COMMIT();
            CP_WAIT1();
        } else {
            CP_WAIT0();
        }
        __syncthreads();

        const uint32_t as = (kb & 1) ? as1 : as0;
        const uint32_t bs = (kb & 1) ? bs1 : bs0;

        #pragma unroll
        for (int ks = 0; ks < 2; ks++) {
            uint32_t a[4][4];
            #pragma unroll
            for (int mi = 0; mi < 4; mi++) {
                int row = wm * 64 + mi * 16 + (lane & 15);
                int col = ks * 16 + (lane >> 4) * 8;
                LDMATRIX_X4(a[mi][0], a[mi][1], a[mi][2], a[mi][3],
                            as + (uint32_t)(row * SSTRIDE + col) * 2);
            }
            uint32_t b[4][2];
            #pragma unroll
            for (int nb = 0; nb < 2; nb++) {
                int nrow = wn * 32 + nb * 16 + ((lane & 16) ? 8 : 0) + (lane & 7);
                int kcol = ks * 16 + ((lane & 8) ? 8 : 0);
                uint32_t r0, r1, r2, r3;
                LDMATRIX_X4(r0, r1, r2, r3,
                            bs + (uint32_t)(nrow * SSTRIDE + kcol) * 2);
                b[nb*2][0] = r0; b[nb*2][1] = r1;
                b[nb*2+1][0] = r2; b[nb*2+1][1] = r3;
            }
            #pragma unroll
            for (int mi = 0; mi < 4; mi++)
                #pragma unroll
                for (int ni = 0; ni < 4; ni++)
                    MMA_BF16(acc[mi][ni][0], acc[mi][ni][1], acc[mi][ni][2], acc[mi][ni][3],
                             a[mi][0], a[mi][1], a[mi][2], a[mi][3],
                             b[ni][0], b[ni][1]);
        }
        __syncthreads();
    }

    #pragma unroll
    for (int mi = 0; mi < 4; mi++) {
        int mrow = m0 + wm * 64 + mi * 16 + (lane >> 2);
        #pragma unroll
        for (int ni = 0; ni < 4; ni++) {
            int ncol = n0 + wn * 32 + ni * 8 + (lane & 3) * 2;
            *(float2*)&C[(size_t)mrow * N + ncol] =
                make_float2(acc[mi][ni][0], acc[mi][ni][1]);
            *(float2*)&C[(size_t)(mrow + 8) * N + ncol] =
                make_float2(acc[mi][ni][2], acc[mi][ni][3]);
        }
    }
}

// ============================================================================
// RoPE -> tensor-ready bf16 operands.
// Qp row: [ scale*rope(q) hi | lo | hi ]  (192)
// Kp row: [ rope(k) hi | hi | lo ]        (192)
// Vph/Vpl: v hi / lo                       (64 each)
// ============================================================================
__global__ __launch_bounds__(256) void rope_pack_kernel(
    const float* __restrict__ qkv,
    const float* __restrict__ sin_q, const float* __restrict__ cos_q,
    const float* __restrict__ sin_k, const float* __restrict__ cos_k,
    __nv_bfloat16* __restrict__ Qp, __nv_bfloat16* __restrict__ Kp,
    __nv_bfloat16* __restrict__ Vph, __nv_bfloat16* __restrict__ Vpl)
{
    int idx = blockIdx.x * blockDim.x + threadIdx.x;
    if (idx >= B_*S_*D_) return;
    int d = idx % HD_;
    int h = (idx / HD_) % H_;
    int s = (idx / D_) % S_;
    int b = idx / (S_ * D_);

    const float* row = qkv + ((size_t)b*S_ + s) * (3*D_);
    int hd = h*HD_ + d;
    int dp = (d < HD_/2) ? d + HD_/2 : d - HD_/2;
    float sgn = (d < HD_/2) ? -1.f : 1.f;

    float qv = row[hd];
    float kv = row[D_ + hd];
    float vv = row[2*D_ + hd];
    float qp = row[h*HD_ + dp];
    float kp = row[D_ + h*HD_ + dp];

    float sq = sin_q[s*HD_ + d], cq = cos_q[s*HD_ + d];
    float sk = sin_k[s*HD_ + d], ck = cos_k[s*HD_ + d];

    float qr = (qv * cq + sgn * qp * sq) * SCALE_;
    float kr = kv * ck + sgn * kp * sk;

    size_t bhs = ((size_t)(b*H_ + h) * S_ + s);

    __nv_bfloat16 qh = __float2bfloat16(qr);
    __nv_bfloat16 ql = __float2bfloat16(qr - __bfloat162float(qh));
    __nv_bfloat16 kh = __float2bfloat16(kr);
    __nv_bfloat16 kl = __float2bfloat16(kr - __bfloat162float(kh));
    __nv_bfloat16 vh = __float2bfloat16(vv);
    __nv_bfloat16 vl = __float2bfloat16(vv - __bfloat162float(vh));

    __nv_bfloat16* qrow = Qp + bhs * AKP_;
    qrow[d] = qh; qrow[64 + d] = ql; qrow[128 + d] = qh;
    __nv_bfloat16* krow = Kp + bhs * AKP_;
    krow[d] = kh; krow[64 + d] = kh; krow[128 + d] = kl;
    Vph[bhs * HD_ + d] = vh;
    Vpl[bhs * HD_ + d] = vl;
}

// ============================================================================
// Tensor-core causal flash attention.
// CTA: 128 queries x one (b,h). 4 warps x 32 rows. 32-key tiles, 2-stage
// cp.async pipeline. QK^T compensated via 192-wide K'; PV compensated via
// in-register P hi/lo split + Vh/Vl.
// ============================================================================
#define AQ 128
#define AK 32
#define QSTR 200   // bf16 elems per Q/K smem row (192 + 8 pad)
#define VSTR 72    // bf16 elems per V smem row  (64 + 8 pad)

// smem element offsets
#define QS_OFF   0
#define KS_OFF   25600           // 128*200
#define KS_STAGE 6400            // 32*200
#define VH_OFF   38400           // KS_OFF + 2*KS_STAGE
#define VS_STAGE 2304            // 32*72
#define VL_OFF   43008           // VH_OFF + 2*VS_STAGE
#define ATTN_SMEM_BYTES ((VL_OFF + 2*VS_STAGE) * 2)   // 95232

__global__ __launch_bounds__(128) void attn_mma_kernel(
    const __nv_bfloat16* __restrict__ Qp, const __nv_bfloat16* __restrict__ Kp,
    const __nv_bfloat16* __restrict__ Vph, const __nv_bfloat16* __restrict__ Vpl,
    float* __restrict__ Oattn)
{
    extern __shared__ __align__(16) __nv_bfloat16 sm[];
    const uint32_t smb = smem_u32(sm);

    const int tid  = threadIdx.x;
    const int wid  = tid >> 5, lane = tid & 31;
    const int bh   = blockIdx.y;
    const int q0   = blockIdx.x * AQ;
    const int qrow0 = q0 + 32 * wid;   // warp's first query row

    const size_t bhS = (size_t)bh * S_;

    // ---- async loaders ----
    auto load_q = [&]() {
        #pragma unroll
        for (int i = 0; i < 24; i++) {
            int idx = tid + i * 128;
            int row = idx / 24, c = idx % 24;
            CP_ASYNC16(smb + (uint32_t)(QS_OFF + row * QSTR + c * 8) * 2,
                       Qp + (bhS + q0 + row) * AKP_ + c * 8);
        }
    };
    auto load_kv = [&](int stage, int kt) {
        int s0 = kt * AK;
        #pragma unroll
        for (int i = 0; i < 6; i++) {
            int idx = tid + i * 128;
            int row = idx / 24, c = idx % 24;
            CP_ASYNC16(smb + (uint32_t)(KS_OFF + stage * KS_STAGE + row * QSTR + c * 8) * 2,
                       Kp + (bhS + s0 + row) * AKP_ + c * 8);
        }
        #pragma unroll
        for (int i = 0; i < 2; i++) {
            int idx = tid + i * 128;
            int row = idx / 8, c = idx % 8;
            CP_ASYNC16(smb + (uint32_t)(VH_OFF + stage * VS_STAGE + row * VSTR + c * 8) * 2,
                       Vph + (bhS + s0 + row) * HD_ + c * 8);
            CP_ASYNC16(smb + (uint32_t)(VL_OFF + stage * VS_STAGE + row * VSTR + c * 8) * 2,
                       Vpl + (bhS + s0 + row) * HD_ + c * 8);
        }
    };

    // ---- state ----
    float O[2][8][4];
    #pragma unroll
    for (int mi = 0; mi < 2; mi++)
        #pragma unroll
        for (int nd = 0; nd < 8; nd++)
            #pragma unroll
            for (int r = 0; r < 4; r++) O[mi][nd][r] = 0.f;
    float mst[2][2] = {{-CUDART_INF_F, -CUDART_INF_F}, {-CUDART_INF_F, -CUDART_INF_F}};
    float lst[2][2] = {{0.f, 0.f}, {0.f, 0.f}};

    const int ntiles = q0 / AK + 4;

    load_q();
    CP_COMMIT();
    load_kv(0, 0);
    CP_COMMIT();

    for (int kt = 0; kt < ntiles; kt++) {
        const int stage = kt & 1;
        if (kt + 1 < ntiles) {
            load_kv((kt + 1) & 1, kt + 1);
            CP_COMMIT();
            CP_WAIT1();
        } else {
            CP_WAIT0();
        }
        __syncthreads();

        const int k0g = kt * AK;
        const bool active = (k0g <= qrow0 + 31);

        if (active) {
            // ---- QK^T (compensated, K'=192) ----
            float c[2][4][4];
            #pragma unroll
            for (int mi = 0; mi < 2; mi++)
                #pragma unroll
                for (int ni = 0; ni < 4; ni++)
                    #pragma unroll
                    for (int r = 0; r < 4; r++) c[mi][ni][r] = 0.f;

            #pragma unroll
            for (int kc = 0; kc < 12; kc++) {
                uint32_t kb[4][2];
                #pragma unroll
                for (int t = 0; t < 2; t++) {
                    int krow = 16*t + (lane & 7) + 8*(lane >> 4);
                    int kcol = kc*16 + 8*((lane >> 3) & 1);
                    uint32_t r0, r1, r2, r3;
                    LDMATRIX_X4(r0, r1, r2, r3,
                        smb + (uint32_t)(KS_OFF + stage*KS_STAGE + krow*QSTR + kcol) * 2);
                    kb[2*t][0] = r0; kb[2*t][1] = r1;
                    kb[2*t+1][0] = r2; kb[2*t+1][1] = r3;
                }
                #pragma unroll
                for (int mi = 0; mi < 2; mi++) {
                    int qrow = 32*wid + 16*mi + (lane & 15);
                    int qcol = kc*16 + 8*(lane >> 4);
                    uint32_t a0, a1, a2, a3;
                    LDMATRIX_X4(a0, a1, a2, a3,
                        smb + (uint32_t)(QS_OFF + qrow*QSTR + qcol) * 2);
                    #pragma unroll
                    for (int ni = 0; ni < 4; ni++)
                        MMA_BF16(c[mi][ni][0], c[mi][ni][1], c[mi][ni][2], c[mi][ni][3],
                                 a0, a1, a2, a3, kb[ni][0], kb[ni][1]);
                }
            }

            // ---- causal mask (diagonal tiles only) ----
            if (k0g + AK - 1 > qrow0) {
                #pragma unroll
                for (int mi = 0; mi < 2; mi++)
                    #pragma unroll
                    for (int ni = 0; ni < 4; ni++)
                        #pragma unroll
                        for (int r = 0; r < 4; r++) {
                            int kk = k0g + ni*8 + 2*(lane & 3) + (r & 1);
                            int qq = qrow0 + 16*mi + (lane >> 2) + ((r >= 2) ? 8 : 0);
                            if (kk > qq) c[mi][ni][r] = -CUDART_INF_F;
                        }
            }

            // ---- online softmax (fp32) ----
            #pragma unroll
            for (int mi = 0; mi < 2; mi++)
                #pragma unroll
                for (int h = 0; h < 2; h++) {
                    float mt = -CUDART_INF_F;
                    #pragma unroll
                    for (int ni = 0; ni < 4; ni++)
                        mt = fmaxf(mt, fmaxf(c[mi][ni][2*h], c[mi][ni][2*h+1]));
                    mt = fmaxf(mt, __shfl_xor_sync(0xffffffffu, mt, 1));
                    mt = fmaxf(mt, __shfl_xor_sync(0xffffffffu, mt, 2));
                    float mnew = fmaxf(mst[mi][h], mt);
                    float corr = __expf(mst[mi][h] - mnew);
                    mst[mi][h] = mnew;
                    float ls = 0.f;
                    #pragma unroll
                    for (int ni = 0; ni < 4; ni++) {
                        float p0 = __expf(c[mi][ni][2*h]   - mnew);
                        float p1 = __expf(c[mi][ni][2*h+1] - mnew);
                        c[mi][ni][2*h] = p0; c[mi][ni][2*h+1] = p1;
                        ls += p0 + p1;
                    }
                    lst[mi][h] = lst[mi][h] * corr + ls;
                    #pragma unroll
                    for (int nd = 0; nd < 8; nd++) {
                        O[mi][nd][2*h]   *= corr;
                        O[mi][nd][2*h+1] *= corr;
                    }
                }

            // ---- PV (compensated: Ph*Vh + Ph*Vl + Pl*Vh) ----
            #pragma unroll
            for (int kc2 = 0; kc2 < 2; kc2++) {
                uint32_t ph[2][4], pl[2][4];
                #pragma unroll
                for (int mi = 0; mi < 2; mi++) {
                    pack_pair(c[mi][2*kc2][0],   c[mi][2*kc2][1],   ph[mi][0], pl[mi][0]);
                    pack_pair(c[mi][2*kc2][2],   c[mi][2*kc2][3],   ph[mi][1], pl[mi][1]);
                    pack_pair(c[mi][2*kc2+1][0], c[mi][2*kc2+1][1], ph[mi][2], pl[mi][2]);
                    pack_pair(c[mi][2*kc2+1][2], c[mi][2*kc2+1][3], ph[mi][3], pl[mi][3]);
                }
                uint32_t vh[8][2], vl[8][2];
                #pragma unroll
                for (int t = 0; t < 4; t++) {
                    int vrow = kc2*16 + (lane & 15);
                    int vcol = 16*t + 8*(lane >> 4);
                    uint32_t r0, r1, r2, r3;
                    LDMATRIX_X4_T(r0, r1, r2, r3,
                        smb + (uint32_t)(VH_OFF + stage*VS_STAGE + vrow*VSTR + vcol) * 2);
                    vh[2*t][0] = r0; vh[2*t][1] = r1;
                    vh[2*t+1][0] = r2; vh[2*t+1][1] = r3;
                    LDMATRIX_X4_T(r0, r1, r2, r3,
                        smb + (uint32_t)(VL_OFF + stage*VS_STAGE + vrow*VSTR + vcol) * 2);
                    vl[2*t][0] = r0; vl[2*t][1] = r1;
                    vl[2*t+1][0] = r2; vl[2*t+1][1] = r3;
                }
                #pragma unroll
                for (int mi = 0; mi < 2; mi++)
                    #pragma unroll
                    for (int nd = 0; nd < 8; nd++) {
                        MMA_BF16(O[mi][nd][0], O[mi][nd][1], O[mi][nd][2], O[mi][nd][3],
                                 ph[mi][0], ph[mi][1], ph[mi][2], ph[mi][3],
                                 vh[nd][0], vh[nd][1]);
                        MMA_BF16(O[mi][nd][0], O[mi][nd][1], O[mi][nd][2], O[mi][nd][3],
                                 ph[mi][0], ph[mi][1], ph[mi][2], ph[mi][3],
                                 vl[nd][0], vl[nd][1]);
                        MMA_BF16(O[mi][nd][0], O[mi][nd][1], O[mi][nd][2], O[mi][nd][3],
                                 pl[mi][0], pl[mi][1], pl[mi][2], pl[mi][3],
                                 vh[nd][0], vh[nd][1]);
                    }
            }
        }
        __syncthreads();
    }

    // ---- normalize + store to [B,S,D] ----
    const int b = bh >> 4, hh = bh & 15;
    #pragma unroll
    for (int mi = 0; mi < 2; mi++)
        #pragma unroll
        for (int h = 0; h < 2; h++) {
            float lt = lst[mi][h];
            lt += __shfl_xor_sync(0xffffffffu, lt, 1);
            lt += __shfl_xor_sync(0xffffffffu, lt, 2);
            float inv = 1.f / lt;
            int row = qrow0 + 16*mi + (lane >> 2) + ((h) ? 8 : 0);
            #pragma unroll
            for (int nd = 0; nd < 8; nd++) {
                int col = hh * HD_ + nd*8 + 2*(lane & 3);
                *(float2*)&Oattn[((size_t)b*S_ + row) * D_ + col] =
                    make_float2(O[mi][nd][2*h] * inv, O[mi][nd][2*h+1] * inv);
            }
        }
}

// ============================================================================
// Launch
// ============================================================================
extern "C" void kernel_launch(void* const* d_in, const int* in_sizes, int n_in,
                              void* d_out, int out_size)
{
    const float* query = (const float*)d_in[0];
    const float* sin_q = (const float*)d_in[1];
    const float* cos_q = (const float*)d_in[2];
    const float* sin_k = (const float*)d_in[3];
    const float* cos_k = (const float*)d_in[4];
    const float* w_in  = (const float*)d_in[5];
    const float* w_out = (const float*)d_in[6];
    float* out = (float*)d_out;

    float *qkv, *attn;
    __nv_bfloat16 *Abig, *W1big, *W2big, *Qp, *Kp, *Vph, *Vpl;
    cudaGetSymbolAddress((void**)&qkv,   g_qkv);
    cudaGetSymbolAddress((void**)&attn,  g_attn);
    cudaGetSymbolAddress((void**)&Abig,  g_Abig);
    cudaGetSymbolAddress((void**)&W1big, g_W1big);
    cudaGetSymbolAddress((void**)&W2big, g_W2big);
    cudaGetSymbolAddress((void**)&Qp,    g_Qp);
    cudaGetSymbolAddress((void**)&Kp,    g_Kp);
    cudaGetSymbolAddress((void**)&Vph,   g_Vph);
    cudaGetSymbolAddress((void**)&Vpl,   g_Vpl);

    static bool attr_set = false;
    if (!attr_set) {
        cudaFuncSetAttribute(attn_mma_kernel,
                             cudaFuncAttributeMaxDynamicSharedMemorySize, ATTN_SMEM_BYTES);
        attr_set = true;
    }

    const int M = B_ * S_;   // 4096

    // Prep: 3-term bf16 encode for projections
    split_a_kernel<<<(M*D_ + 255)/256, 256>>>(query, Abig, M*D_);
    transpose_split_w_kernel<<<dim3(3*D_/32, D_/32), dim3(32,8)>>>(w_in,  W1big, 3*D_);
    transpose_split_w_kernel<<<dim3(D_/32,   D_/32), dim3(32,8)>>>(w_out, W2big, D_);

    // 1) QKV projection (tensor cores)
    gemm_mma_kernel<<<dim3(3*D_/GBN, M/GBM), 256>>>(Abig, W1big, qkv, M, 3*D_);

    // 2) RoPE + pack tensor operands
    rope_pack_kernel<<<(B_*S_*D_ + 255)/256, 256>>>(
        qkv, sin_q, cos_q, sin_k, cos_k, Qp, Kp, Vph, Vpl);

    // 3) Tensor-core causal flash attention
    attn_mma_kernel<<<dim3(S_/AQ, B_*H_), 128, ATTN_SMEM_BYTES>>>(Qp, Kp, Vph, Vpl, attn);

    // 4) Output projection (tensor cores)
    split_a_kernel<<<(M*D_ + 255)/256, 256>>>(attn, Abig, M*D_);
    gemm_mma_kernel<<<dim3(D_/GBN, M/GBM), 256>>>(Abig, W2big, out, M, D_);
}